// round 13
// baseline (speedup 1.0000x reference)
#include <cuda_runtime.h>
#include <math.h>

#define Bb 128
#define Tt 100
#define Dd 2048
#define Hh 1024
#define Oo 20
#define BH (Bb*Hh)          // 131072
#define TW 91               // T - W + 1
#define NCONS 128
#define NPROD 160
#define NTILES (Tt*8)       // 800: 8 n-tiles per t-slice

typedef unsigned long long ull;

__device__ __forceinline__ void ffma2(ull& d, ull a, ull b) {
    asm("fma.rn.f32x2 %0, %1, %2, %0;" : "+l"(d) : "l"(a), "l"(b));
}
__device__ __forceinline__ ull bcast2(float x) {
    ull r; unsigned xi = __float_as_uint(x);
    asm("mov.b64 %0, {%1, %2};" : "=l"(r) : "r"(xi), "r"(xi));
    return r;
}
union f4u2 { float4 f; ull u[2]; };

// ---------------- device scratch ----------
__device__ float g_A[Tt*BH];         // input projection G1, layout [t][b][h]
__device__ float g_S[Tt*BH];         // spike history [t][b*H+h]
__device__ float g_WT[Hh*Hh];        // Wh2h transposed: WT[k][n]
__device__ float g_osum[Bb*Oo];
__device__ float g_nbr[Tt];
__device__ int   g_ready[Tt];        // producer->consumer slice flags
__device__ int   g_tileCtr;          // dynamic producer work-stealing counter

// ---------------- init -------------------------------------------------------
__global__ void k_init() {
    int idx = blockIdx.x * blockDim.x + threadIdx.x;
    if (idx < Tt) { g_nbr[idx] = 0.f; g_ready[idx] = 0; }
    if (idx == Tt) g_tileCtr = 0;
}

// ---------------- transpose Wh2h -> WT[k][n] --------------------------------
__global__ __launch_bounds__(256) void k_transp(const float* __restrict__ W) {
    __shared__ float tile[32][33];
    int bx = blockIdx.x % 32, by = blockIdx.x / 32;
    int lx = threadIdx.x & 31, ly = threadIdx.x >> 5;
#pragma unroll
    for (int r = 0; r < 4; r++) {
        int n = by * 32 + ly + r * 8;
        tile[ly + r * 8][lx] = W[(size_t)n * Hh + bx * 32 + lx];
    }
    __syncthreads();
#pragma unroll
    for (int r = 0; r < 4; r++) {
        int k = bx * 32 + ly + r * 8;
        g_WT[(size_t)k * Hh + by * 32 + lx] = tile[lx][ly + r * 8];
    }
}

// ---------------- shared-memory union ---------------------------------------
struct SmemProd {
    float As[2][16][132];
    float Bs[2][16][132];
};
struct SmemCons {
    float sflag[Hh];
    int   list[Hh];
    float red[256];
    float rs[Oo][128];
    float spsm[Oo];
    float omem[Oo];
    float osum[Oo];
    int   cnt;
};
union SmemU {
    SmemProd p;
    SmemCons c;
    float    filt[128 * TW];   // consumer tail: filter staging (46.6KB)
};

// ---------------- the persistent everything kernel --------------------------
// grid 288 x 256, __launch_bounds__(256,2): all blocks resident wave 0.
//   blocks 0..127   : consumer — 100-step recursion for batch b=bid + filter
//   blocks 128..287 : producers — f32x2 input-GEMM tiles, WORK-STEALING order
__global__ __launch_bounds__(256, 2) void k_run(
    const float* __restrict__ X,   const float* __restrict__ W1,
    const float* __restrict__ hs0, const float* __restrict__ hm0,
    const float* __restrict__ om0,
    const float* __restrict__ b1,  const float* __restrict__ b2,
    const float* __restrict__ thr_h,
    const float* __restrict__ W2,  const float* __restrict__ b2o,
    const float* __restrict__ thr_o,
    float* __restrict__ out)
{
    __shared__ SmemU sm;
    __shared__ int s_tile;
    const int tid = threadIdx.x;
    const int bid = blockIdx.x;

    if (bid >= NCONS) {
        // ================= PRODUCER (dynamic work stealing) =================
        const int lr = tid >> 2;
        const int lc = (tid & 3) << 2;
        const int tm = tid & 15, tn = tid >> 4;

        for (;;) {
            if (tid == 0) s_tile = atomicAdd(&g_tileCtr, 1);
            __syncthreads();
            const int id = s_tile;
            if (id >= NTILES) return;
            const int t  = id >> 3;
            const int n0 = (id & 7) * 128;

            ull c2[8][4];
#pragma unroll
            for (int i = 0; i < 8; i++)
#pragma unroll
                for (int p = 0; p < 4; p++) c2[i][p] = 0ULL;

            const float* pa0 = X + (size_t)lr * (Tt * Dd) + (size_t)t * Dd + lc;
            const float* pa1 = X + (size_t)(lr + 64) * (Tt * Dd) + (size_t)t * Dd + lc;
            const float* pb0 = W1 + (size_t)(n0 + lr) * Dd + lc;
            const float* pb1 = W1 + (size_t)(n0 + lr + 64) * Dd + lc;

            float4 ra0 = *(const float4*)(pa0);
            float4 ra1 = *(const float4*)(pa1);
            float4 rb0 = *(const float4*)(pb0);
            float4 rb1 = *(const float4*)(pb1);
#pragma unroll
            for (int j = 0; j < 4; j++) {
                sm.p.As[0][lc + j][lr]      = ((const float*)&ra0)[j];
                sm.p.As[0][lc + j][lr + 64] = ((const float*)&ra1)[j];
                sm.p.Bs[0][lc + j][lr]      = ((const float*)&rb0)[j];
                sm.p.Bs[0][lc + j][lr + 64] = ((const float*)&rb1)[j];
            }
            __syncthreads();

            const int NK = Dd / 16;
            int buf = 0;
            for (int kt = 0; kt < NK; ++kt) {
                if (kt + 1 < NK) {
                    int ko = (kt + 1) * 16;
                    ra0 = *(const float4*)(pa0 + ko);
                    ra1 = *(const float4*)(pa1 + ko);
                    rb0 = *(const float4*)(pb0 + ko);
                    rb1 = *(const float4*)(pb1 + ko);
                }
#pragma unroll
                for (int kk = 0; kk < 16; ++kk) {
                    float4 a0 = *(const float4*)&sm.p.As[buf][kk][tm * 4];
                    float4 a1 = *(const float4*)&sm.p.As[buf][kk][tm * 4 + 64];
                    f4u2 b0u, b1u;
                    b0u.f = *(const float4*)&sm.p.Bs[buf][kk][tn * 4];
                    b1u.f = *(const float4*)&sm.p.Bs[buf][kk][tn * 4 + 64];
                    ull bp[4] = {b0u.u[0], b0u.u[1], b1u.u[0], b1u.u[1]};
                    float av[8] = {a0.x,a0.y,a0.z,a0.w,a1.x,a1.y,a1.z,a1.w};
#pragma unroll
                    for (int i = 0; i < 8; i++) {
                        ull ap = bcast2(av[i]);
#pragma unroll
                        for (int p = 0; p < 4; p++) ffma2(c2[i][p], ap, bp[p]);
                    }
                }
                if (kt + 1 < NK) {
                    int nb = buf ^ 1;
#pragma unroll
                    for (int j = 0; j < 4; j++) {
                        sm.p.As[nb][lc + j][lr]      = ((const float*)&ra0)[j];
                        sm.p.As[nb][lc + j][lr + 64] = ((const float*)&ra1)[j];
                        sm.p.Bs[nb][lc + j][lr]      = ((const float*)&rb0)[j];
                        sm.p.Bs[nb][lc + j][lr + 64] = ((const float*)&rb1)[j];
                    }
                }
                buf ^= 1;
                __syncthreads();
            }

#pragma unroll
            for (int i = 0; i < 8; i++) {
                int row = tm * 4 + (i & 3) + ((i >= 4) ? 64 : 0);
#pragma unroll
                for (int jg = 0; jg < 2; jg++) {
                    f4u2 v;
                    v.u[0] = c2[i][2 * jg];
                    v.u[1] = c2[i][2 * jg + 1];
                    *(float4*)&g_A[((size_t)t * Bb + row) * Hh + n0 + tn * 4 + jg * 64] = v.f;
                }
            }
            __threadfence();
            __syncthreads();
            if (tid == 0) atomicAdd(&g_ready[t], 1);
        }
    }

    // ================= CONSUMER: batch b = bid, all 100 steps =================
    const int b = bid;

    float4 hm4 = *(const float4*)&hm0[(size_t)b * Hh + tid * 4];
    float mreg[4] = {hm4.x, hm4.y, hm4.z, hm4.w};
    float4 bb1 = *(const float4*)&b1[tid * 4];
    float4 bb2 = *(const float4*)&b2[tid * 4];
    float4 th4 = *(const float4*)&thr_h[tid * 4];
    float b1v[4] = {bb1.x, bb1.y, bb1.z, bb1.w};
    float b2v[4] = {bb2.x, bb2.y, bb2.z, bb2.w};
    float thv[4] = {th4.x, th4.y, th4.z, th4.w};

    *(float4*)&sm.c.sflag[tid * 4] = *(const float4*)&hs0[(size_t)b * Hh + tid * 4];
    if (tid < Oo) {
        sm.c.omem[tid] = om0[b * Oo + tid];
        sm.c.osum[tid] = 0.f;
    }
    __syncthreads();

    for (int t = 0; t < Tt; ++t) {
        // ---- ordered stream compaction of active k (warp 0) ----
        if (tid < 32) {
            int base = 0;
            for (int c = 0; c < 32; ++c) {
                float v = sm.c.sflag[c * 32 + tid];
                unsigned m = __ballot_sync(0xffffffffu, v != 0.f);
                if (v != 0.f) {
                    int pre = __popc(m & ((1u << tid) - 1u));
                    sm.c.list[base + pre] = c * 32 + tid;
                }
                base += __popc(m);
            }
            if (tid == 0) sm.c.cnt = base;
        }
        __syncthreads();
        const int cnt = sm.c.cnt;

        // ---- sparse gather: acc[n] = sum_{active k asc} WT[k][n] ----
        float a0 = 0.f, a1 = 0.f, a2 = 0.f, a3 = 0.f;
        int j = 0;
        for (; j + 4 <= cnt; j += 4) {
            int k0 = sm.c.list[j], k1 = sm.c.list[j + 1];
            int k2 = sm.c.list[j + 2], k3 = sm.c.list[j + 3];
            float4 w0 = *(const float4*)&g_WT[(size_t)k0 * Hh + tid * 4];
            float4 w1 = *(const float4*)&g_WT[(size_t)k1 * Hh + tid * 4];
            float4 w2 = *(const float4*)&g_WT[(size_t)k2 * Hh + tid * 4];
            float4 w3 = *(const float4*)&g_WT[(size_t)k3 * Hh + tid * 4];
            a0 += w0.x; a1 += w0.y; a2 += w0.z; a3 += w0.w;
            a0 += w1.x; a1 += w1.y; a2 += w1.z; a3 += w1.w;
            a0 += w2.x; a1 += w2.y; a2 += w2.z; a3 += w2.w;
            a0 += w3.x; a1 += w3.y; a2 += w3.z; a3 += w3.w;
        }
        for (; j < cnt; ++j) {
            int k = sm.c.list[j];
            float4 w = *(const float4*)&g_WT[(size_t)k * Hh + tid * 4];
            a0 += w.x; a1 += w.y; a2 += w.z; a3 += w.w;
        }

        // ---- wait for input slice t ----
        if (tid == 0) {
            while (*((volatile int*)&g_ready[t]) < 8) __nanosleep(64);
            __threadfence();
        }
        __syncthreads();

        // ---- hidden membrane update ----
        float accs[4] = {a0, a1, a2, a3};
        float4 G1 = *(const float4*)&g_A[((size_t)t * Bb + b) * Hh + tid * 4];
        float g1v[4] = {G1.x, G1.y, G1.z, G1.w};
        float spv[4];
        float spsum = 0.f;
#pragma unroll
        for (int e = 0; e < 4; e++) {
            float v = ((g1v[e] + b1v[e]) + accs[e]) + b2v[e];
            float mem = mreg[e] + v;
            float th = thv[e];
            float sp = (mem - th > 0.f) ? 1.f : 0.f;
            mem = mem * (1.f - sp);
            float neg = (mem < -th) ? 1.f : 0.f;
            mem = mem * (1.f - neg) - th * neg;
            mreg[e] = mem;
            spv[e] = sp;
            spsum += sp;
        }
        float4 spq = make_float4(spv[0], spv[1], spv[2], spv[3]);
        *(float4*)&g_S[(size_t)t * BH + b * Hh + tid * 4] = spq;
        *(float4*)&sm.c.sflag[tid * 4] = spq;

        sm.c.red[tid] = spsum;
        __syncthreads();
        for (int s = 128; s > 0; s >>= 1) {
            if (tid < s) sm.c.red[tid] += sm.c.red[tid + s];
            __syncthreads();
        }
        if (tid == 0) atomicAdd(&g_nbr[t], sm.c.red[0] * (1.f / Bb));

        // ---- output layer for step t (spikes from smem, bit-identical) ----
        if (tid < 128) {
            float acc[Oo];
#pragma unroll
            for (int o = 0; o < Oo; o++) acc[o] = 0.f;
            for (int k = tid; k < Hh; k += 128) {
                float h = sm.c.sflag[k];
#pragma unroll
                for (int o = 0; o < Oo; o++) acc[o] = fmaf(h, W2[o * Hh + k], acc[o]);
            }
#pragma unroll
            for (int o = 0; o < Oo; o++) sm.c.rs[o][tid] = acc[o];
        }
        __syncthreads();
        for (int s = 64; s > 0; s >>= 1) {
            if (tid < s)
#pragma unroll
                for (int o = 0; o < Oo; o++) sm.c.rs[o][tid] += sm.c.rs[o][tid + s];
            __syncthreads();
        }
        if (tid < Oo) {
            int o = tid;
            float m = sm.c.omem[o] + (sm.c.rs[o][0] + b2o[o]);
            float th = thr_o[o];
            float sp = (m - th > 0.f) ? 1.f : 0.f;
            m = m * (1.f - sp);
            float neg = (m < -th) ? 1.f : 0.f;
            m = m * (1.f - neg) - th * neg;
            sm.c.omem[o] = m;
            sm.c.osum[o] += sp;
            sm.c.spsm[o] = sp;
        }
        __syncthreads();
        if (tid == 0) {
            float s = 0.f;
            for (int o = 0; o < Oo; o++) s += sm.c.spsm[o];
            atomicAdd(&g_nbr[t], s * (1.f / Bb));
        }
        __syncthreads();
    }

    if (tid < Oo) g_osum[b * Oo + tid] = sm.c.osum[tid];
    __syncthreads();   // consumer state dead; union reused for filter staging

    // ---- fused sliding-window filter for this batch (bit-exact) ----
    for (int chunk = 0; chunk < Hh / 128; ++chunk) {
        if (tid < 128) {
            int h = chunk * 128 + tid;
            const float* S = g_S + (size_t)b * Hh + h;
            float s = 0.f;
#pragma unroll
            for (int tt = 0; tt < 10; ++tt) s += S[(size_t)tt * BH];
            sm.filt[tid * TW + 0] = s / 10.0f;
            for (int tt = 10; tt < Tt; ++tt) {
                s += S[(size_t)tt * BH] - S[(size_t)(tt - 10) * BH];
                sm.filt[tid * TW + (tt - 9)] = s / 10.0f;
            }
        }
        __syncthreads();
        float* dst = out + 229 + ((size_t)b * Hh + chunk * 128) * TW;
        for (int idx = tid; idx < 128 * TW; idx += 256) dst[idx] = sm.filt[idx];
        __syncthreads();
    }
}

// ---------------- predictions / loss / nbr_events --------------------------
__global__ void k_final(const int* __restrict__ labels, float* __restrict__ out) {
    int tid = threadIdx.x;  // 256 threads
    __shared__ float red[128];
    if (tid < 128) {
        int b = tid;
        float mx = g_osum[b * Oo];
        int arg = 0;
        for (int o = 1; o < Oo; o++) {
            float v = g_osum[b * Oo + o];
            if (v > mx) { mx = v; arg = o; }
        }
        float se = 0.f;
        for (int o = 0; o < Oo; o++) se += expf(g_osum[b * Oo + o] - mx);
        float lse = mx + logf(se);
        out[b] = (float)arg;
        int lab = labels[b];
        red[b] = -(g_osum[b * Oo + lab] - lse);
    }
    __syncthreads();
    for (int s = 64; s > 0; s >>= 1) {
        if (tid < s) red[tid] += red[tid + s];
        __syncthreads();
    }
    if (tid == 0) out[128] = red[0] / (float)Bb;
    if (tid >= 128 && tid < 128 + Tt) out[129 + (tid - 128)] = g_nbr[tid - 128];
}

// ---------------- launcher --------------------------------------------------
extern "C" void kernel_launch(void* const* d_in, const int* in_sizes, int n_in,
                              void* d_out, int out_size) {
    const float* input = (const float*)d_in[0];
    const int*   labels = (const int*)d_in[1];
    const float* hmem0 = (const float*)d_in[2];
    const float* hspk0 = (const float*)d_in[3];
    const float* omem0 = (const float*)d_in[4];
    const float* Wi2h  = (const float*)d_in[6];
    const float* bi2h  = (const float*)d_in[7];
    const float* Wh2h  = (const float*)d_in[8];
    const float* bh2h  = (const float*)d_in[9];
    const float* Wh2o  = (const float*)d_in[10];
    const float* bh2o  = (const float*)d_in[11];
    const float* thr_h = (const float*)d_in[12];
    const float* thr_o = (const float*)d_in[13];
    float* out = (float*)d_out;

    k_init<<<1, 128>>>();
    k_transp<<<1024, 256>>>(Wh2h);
    k_run<<<NCONS + NPROD, 256>>>(input, Wi2h, hspk0, hmem0, omem0,
                                  bi2h, bh2h, thr_h, Wh2o, bh2o, thr_o, out);
    k_final<<<1, 256>>>(labels, out);
}

// round 14
// speedup vs baseline: 1.0647x; 1.0647x over previous
#include <cuda_runtime.h>
#include <math.h>

#define Bb 128
#define Tt 100
#define Dd 2048
#define Hh 1024
#define Oo 20
#define BH (Bb*Hh)          // 131072
#define TW 91               // T - W + 1
#define NCONS 128
#define NPROD 148
#define NTILES (Tt*8)       // 800: 8 n-tiles per t-slice

typedef unsigned long long ull;

__device__ __forceinline__ void ffma2(ull& d, ull a, ull b) {
    asm("fma.rn.f32x2 %0, %1, %2, %0;" : "+l"(d) : "l"(a), "l"(b));
}
__device__ __forceinline__ ull bcast2(float x) {
    ull r; unsigned xi = __float_as_uint(x);
    asm("mov.b64 %0, {%1, %2};" : "=l"(r) : "r"(xi), "r"(xi));
    return r;
}
union f4u2 { float4 f; ull u[2]; };

// ---------------- device scratch ----------
__device__ float g_A[Tt*BH];         // input projection G1, layout [t][b][h]
__device__ float g_S[Tt*BH];         // spike history [t][b*H+h]
__device__ float g_WT[Hh*Hh];        // Wh2h transposed: WT[k][n]
__device__ float g_osum[Bb*Oo];
__device__ float g_nbr[Tt];
__device__ int   g_ready[Tt];        // producer->consumer slice flags

// ---------------- init -------------------------------------------------------
__global__ void k_init() {
    int idx = blockIdx.x * blockDim.x + threadIdx.x;
    if (idx < Tt) { g_nbr[idx] = 0.f; g_ready[idx] = 0; }
}

// ---------------- transpose Wh2h -> WT[k][n] --------------------------------
__global__ __launch_bounds__(256) void k_transp(const float* __restrict__ W) {
    __shared__ float tile[32][33];
    int bx = blockIdx.x % 32, by = blockIdx.x / 32;
    int lx = threadIdx.x & 31, ly = threadIdx.x >> 5;
#pragma unroll
    for (int r = 0; r < 4; r++) {
        int n = by * 32 + ly + r * 8;
        tile[ly + r * 8][lx] = W[(size_t)n * Hh + bx * 32 + lx];
    }
    __syncthreads();
#pragma unroll
    for (int r = 0; r < 4; r++) {
        int k = bx * 32 + ly + r * 8;
        g_WT[(size_t)k * Hh + by * 32 + lx] = tile[lx][ly + r * 8];
    }
}

// ---------------- shared-memory union ---------------------------------------
struct SmemProd {
    float As[2][16][132];
    float Bs[2][16][132];
};
struct SmemCons {
    float sflag[Hh];
    int   list[Hh];
    float red[256];
    float rs[Oo][128];
    float spsm[Oo];
    float omem[Oo];
    float osum[Oo];
    int   cnt;
};
union SmemU { SmemProd p; SmemCons c; };

// ---------------- the persistent everything kernel --------------------------
// grid 276 x 256, __launch_bounds__(256,2): all blocks resident wave 0, and
// with modular placement NO SM hosts two producers (this bound R11's makespan).
//   blocks 0..127   : consumer — full 100-step recursion for batch b=bid
//   blocks 128..275 : producers — f32x2 input-GEMM tiles, static stride
__global__ __launch_bounds__(256, 2) void k_run(
    const float* __restrict__ X,   const float* __restrict__ W1,
    const float* __restrict__ hs0, const float* __restrict__ hm0,
    const float* __restrict__ om0,
    const float* __restrict__ b1,  const float* __restrict__ b2,
    const float* __restrict__ thr_h,
    const float* __restrict__ W2,  const float* __restrict__ b2o,
    const float* __restrict__ thr_o)
{
    __shared__ SmemU sm;
    const int tid = threadIdx.x;
    const int bid = blockIdx.x;

    if (bid >= NCONS) {
        // ================= PRODUCER =================
        const int lr = tid >> 2;
        const int lc = (tid & 3) << 2;
        const int tm = tid & 15, tn = tid >> 4;

        for (int id = bid - NCONS; id < NTILES; id += NPROD) {
            const int t  = id >> 3;
            const int n0 = (id & 7) * 128;

            ull c2[8][4];
#pragma unroll
            for (int i = 0; i < 8; i++)
#pragma unroll
                for (int p = 0; p < 4; p++) c2[i][p] = 0ULL;

            const float* pa0 = X + (size_t)lr * (Tt * Dd) + (size_t)t * Dd + lc;
            const float* pa1 = X + (size_t)(lr + 64) * (Tt * Dd) + (size_t)t * Dd + lc;
            const float* pb0 = W1 + (size_t)(n0 + lr) * Dd + lc;
            const float* pb1 = W1 + (size_t)(n0 + lr + 64) * Dd + lc;

            float4 ra0 = *(const float4*)(pa0);
            float4 ra1 = *(const float4*)(pa1);
            float4 rb0 = *(const float4*)(pb0);
            float4 rb1 = *(const float4*)(pb1);
#pragma unroll
            for (int j = 0; j < 4; j++) {
                sm.p.As[0][lc + j][lr]      = ((const float*)&ra0)[j];
                sm.p.As[0][lc + j][lr + 64] = ((const float*)&ra1)[j];
                sm.p.Bs[0][lc + j][lr]      = ((const float*)&rb0)[j];
                sm.p.Bs[0][lc + j][lr + 64] = ((const float*)&rb1)[j];
            }
            __syncthreads();

            const int NK = Dd / 16;
            int buf = 0;
            for (int kt = 0; kt < NK; ++kt) {
                if (kt + 1 < NK) {
                    int ko = (kt + 1) * 16;
                    ra0 = *(const float4*)(pa0 + ko);
                    ra1 = *(const float4*)(pa1 + ko);
                    rb0 = *(const float4*)(pb0 + ko);
                    rb1 = *(const float4*)(pb1 + ko);
                }
#pragma unroll
                for (int kk = 0; kk < 16; ++kk) {
                    float4 a0 = *(const float4*)&sm.p.As[buf][kk][tm * 4];
                    float4 a1 = *(const float4*)&sm.p.As[buf][kk][tm * 4 + 64];
                    f4u2 b0u, b1u;
                    b0u.f = *(const float4*)&sm.p.Bs[buf][kk][tn * 4];
                    b1u.f = *(const float4*)&sm.p.Bs[buf][kk][tn * 4 + 64];
                    ull bp[4] = {b0u.u[0], b0u.u[1], b1u.u[0], b1u.u[1]};
                    float av[8] = {a0.x,a0.y,a0.z,a0.w,a1.x,a1.y,a1.z,a1.w};
#pragma unroll
                    for (int i = 0; i < 8; i++) {
                        ull ap = bcast2(av[i]);
#pragma unroll
                        for (int p = 0; p < 4; p++) ffma2(c2[i][p], ap, bp[p]);
                    }
                }
                if (kt + 1 < NK) {
                    int nb = buf ^ 1;
#pragma unroll
                    for (int j = 0; j < 4; j++) {
                        sm.p.As[nb][lc + j][lr]      = ((const float*)&ra0)[j];
                        sm.p.As[nb][lc + j][lr + 64] = ((const float*)&ra1)[j];
                        sm.p.Bs[nb][lc + j][lr]      = ((const float*)&rb0)[j];
                        sm.p.Bs[nb][lc + j][lr + 64] = ((const float*)&rb1)[j];
                    }
                }
                buf ^= 1;
                __syncthreads();
            }

#pragma unroll
            for (int i = 0; i < 8; i++) {
                int row = tm * 4 + (i & 3) + ((i >= 4) ? 64 : 0);
#pragma unroll
                for (int jg = 0; jg < 2; jg++) {
                    f4u2 v;
                    v.u[0] = c2[i][2 * jg];
                    v.u[1] = c2[i][2 * jg + 1];
                    *(float4*)&g_A[((size_t)t * Bb + row) * Hh + n0 + tn * 4 + jg * 64] = v.f;
                }
            }
            __threadfence();
            __syncthreads();
            if (tid == 0) atomicAdd(&g_ready[t], 1);
        }
        return;
    }

    // ================= CONSUMER: batch b = bid, all 100 steps =================
    const int b = bid;

    float4 hm4 = *(const float4*)&hm0[(size_t)b * Hh + tid * 4];
    float mreg[4] = {hm4.x, hm4.y, hm4.z, hm4.w};
    float4 bb1 = *(const float4*)&b1[tid * 4];
    float4 bb2 = *(const float4*)&b2[tid * 4];
    float4 th4 = *(const float4*)&thr_h[tid * 4];
    float b1v[4] = {bb1.x, bb1.y, bb1.z, bb1.w};
    float b2v[4] = {bb2.x, bb2.y, bb2.z, bb2.w};
    float thv[4] = {th4.x, th4.y, th4.z, th4.w};

    *(float4*)&sm.c.sflag[tid * 4] = *(const float4*)&hs0[(size_t)b * Hh + tid * 4];
    if (tid < Oo) {
        sm.c.omem[tid] = om0[b * Oo + tid];
        sm.c.osum[tid] = 0.f;
    }
    __syncthreads();

    for (int t = 0; t < Tt; ++t) {
        // ---- ordered stream compaction of active k (warp 0) ----
        if (tid < 32) {
            int base = 0;
            for (int c = 0; c < 32; ++c) {
                float v = sm.c.sflag[c * 32 + tid];
                unsigned m = __ballot_sync(0xffffffffu, v != 0.f);
                if (v != 0.f) {
                    int pre = __popc(m & ((1u << tid) - 1u));
                    sm.c.list[base + pre] = c * 32 + tid;
                }
                base += __popc(m);
            }
            if (tid == 0) sm.c.cnt = base;
        }
        __syncthreads();
        const int cnt = sm.c.cnt;

        // ---- sparse gather: acc[n] = sum_{active k asc} WT[k][n] ----
        float a0 = 0.f, a1 = 0.f, a2 = 0.f, a3 = 0.f;
        int j = 0;
        for (; j + 4 <= cnt; j += 4) {
            int k0 = sm.c.list[j], k1 = sm.c.list[j + 1];
            int k2 = sm.c.list[j + 2], k3 = sm.c.list[j + 3];
            float4 w0 = *(const float4*)&g_WT[(size_t)k0 * Hh + tid * 4];
            float4 w1 = *(const float4*)&g_WT[(size_t)k1 * Hh + tid * 4];
            float4 w2 = *(const float4*)&g_WT[(size_t)k2 * Hh + tid * 4];
            float4 w3 = *(const float4*)&g_WT[(size_t)k3 * Hh + tid * 4];
            a0 += w0.x; a1 += w0.y; a2 += w0.z; a3 += w0.w;
            a0 += w1.x; a1 += w1.y; a2 += w1.z; a3 += w1.w;
            a0 += w2.x; a1 += w2.y; a2 += w2.z; a3 += w2.w;
            a0 += w3.x; a1 += w3.y; a2 += w3.z; a3 += w3.w;
        }
        for (; j < cnt; ++j) {
            int k = sm.c.list[j];
            float4 w = *(const float4*)&g_WT[(size_t)k * Hh + tid * 4];
            a0 += w.x; a1 += w.y; a2 += w.z; a3 += w.w;
        }

        // ---- wait for input slice t ----
        if (tid == 0) {
            while (*((volatile int*)&g_ready[t]) < 8) __nanosleep(64);
            __threadfence();
        }
        __syncthreads();

        // ---- hidden membrane update ----
        float accs[4] = {a0, a1, a2, a3};
        float4 G1 = *(const float4*)&g_A[((size_t)t * Bb + b) * Hh + tid * 4];
        float g1v[4] = {G1.x, G1.y, G1.z, G1.w};
        float spv[4];
        float spsum = 0.f;
#pragma unroll
        for (int e = 0; e < 4; e++) {
            float v = ((g1v[e] + b1v[e]) + accs[e]) + b2v[e];
            float mem = mreg[e] + v;
            float th = thv[e];
            float sp = (mem - th > 0.f) ? 1.f : 0.f;
            mem = mem * (1.f - sp);
            float neg = (mem < -th) ? 1.f : 0.f;
            mem = mem * (1.f - neg) - th * neg;
            mreg[e] = mem;
            spv[e] = sp;
            spsum += sp;
        }
        float4 spq = make_float4(spv[0], spv[1], spv[2], spv[3]);
        *(float4*)&g_S[(size_t)t * BH + b * Hh + tid * 4] = spq;
        *(float4*)&sm.c.sflag[tid * 4] = spq;

        sm.c.red[tid] = spsum;
        __syncthreads();
        for (int s = 128; s > 0; s >>= 1) {
            if (tid < s) sm.c.red[tid] += sm.c.red[tid + s];
            __syncthreads();
        }
        if (tid == 0) atomicAdd(&g_nbr[t], sm.c.red[0] * (1.f / Bb));

        // ---- output layer for step t (spikes from smem, bit-identical) ----
        if (tid < 128) {
            float acc[Oo];
#pragma unroll
            for (int o = 0; o < Oo; o++) acc[o] = 0.f;
            for (int k = tid; k < Hh; k += 128) {
                float h = sm.c.sflag[k];
#pragma unroll
                for (int o = 0; o < Oo; o++) acc[o] = fmaf(h, W2[o * Hh + k], acc[o]);
            }
#pragma unroll
            for (int o = 0; o < Oo; o++) sm.c.rs[o][tid] = acc[o];
        }
        __syncthreads();
        for (int s = 64; s > 0; s >>= 1) {
            if (tid < s)
#pragma unroll
                for (int o = 0; o < Oo; o++) sm.c.rs[o][tid] += sm.c.rs[o][tid + s];
            __syncthreads();
        }
        if (tid < Oo) {
            int o = tid;
            float m = sm.c.omem[o] + (sm.c.rs[o][0] + b2o[o]);
            float th = thr_o[o];
            float sp = (m - th > 0.f) ? 1.f : 0.f;
            m = m * (1.f - sp);
            float neg = (m < -th) ? 1.f : 0.f;
            m = m * (1.f - neg) - th * neg;
            sm.c.omem[o] = m;
            sm.c.osum[o] += sp;
            sm.c.spsm[o] = sp;
        }
        __syncthreads();
        if (tid == 0) {
            float s = 0.f;
            for (int o = 0; o < Oo; o++) s += sm.c.spsm[o];
            atomicAdd(&g_nbr[t], s * (1.f / Bb));
        }
        __syncthreads();
    }

    if (tid < Oo) g_osum[b * Oo + tid] = sm.c.osum[tid];
}

// ---------------- sliding-window filter ------------------------------------
__global__ __launch_bounds__(128) void k_filt(float* __restrict__ out) {
    __shared__ float smf[128 * TW];
    int bh = blockIdx.x * 128 + threadIdx.x;
    const float* S = g_S + bh;
    float s = 0.f;
#pragma unroll
    for (int tt = 0; tt < 10; ++tt) s += S[(size_t)tt * BH];
    smf[threadIdx.x * TW + 0] = s / 10.0f;
    for (int tt = 10; tt < Tt; ++tt) {
        s += S[(size_t)tt * BH] - S[(size_t)(tt - 10) * BH];
        smf[threadIdx.x * TW + (tt - 9)] = s / 10.0f;
    }
    __syncthreads();
    float* dst = out + 229 + (size_t)blockIdx.x * 128 * TW;
    for (int idx = threadIdx.x; idx < 128 * TW; idx += 128) dst[idx] = smf[idx];
}

// ---------------- predictions / loss / nbr_events --------------------------
__global__ void k_final(const int* __restrict__ labels, float* __restrict__ out) {
    int tid = threadIdx.x;  // 256 threads
    __shared__ float red[128];
    if (tid < 128) {
        int b = tid;
        float mx = g_osum[b * Oo];
        int arg = 0;
        for (int o = 1; o < Oo; o++) {
            float v = g_osum[b * Oo + o];
            if (v > mx) { mx = v; arg = o; }
        }
        float se = 0.f;
        for (int o = 0; o < Oo; o++) se += expf(g_osum[b * Oo + o] - mx);
        float lse = mx + logf(se);
        out[b] = (float)arg;
        int lab = labels[b];
        red[b] = -(g_osum[b * Oo + lab] - lse);
    }
    __syncthreads();
    for (int s = 64; s > 0; s >>= 1) {
        if (tid < s) red[tid] += red[tid + s];
        __syncthreads();
    }
    if (tid == 0) out[128] = red[0] / (float)Bb;
    if (tid >= 128 && tid < 128 + Tt) out[129 + (tid - 128)] = g_nbr[tid - 128];
}

// ---------------- launcher --------------------------------------------------
extern "C" void kernel_launch(void* const* d_in, const int* in_sizes, int n_in,
                              void* d_out, int out_size) {
    const float* input = (const float*)d_in[0];
    const int*   labels = (const int*)d_in[1];
    const float* hmem0 = (const float*)d_in[2];
    const float* hspk0 = (const float*)d_in[3];
    const float* omem0 = (const float*)d_in[4];
    const float* Wi2h  = (const float*)d_in[6];
    const float* bi2h  = (const float*)d_in[7];
    const float* Wh2h  = (const float*)d_in[8];
    const float* bh2h  = (const float*)d_in[9];
    const float* Wh2o  = (const float*)d_in[10];
    const float* bh2o  = (const float*)d_in[11];
    const float* thr_h = (const float*)d_in[12];
    const float* thr_o = (const float*)d_in[13];
    float* out = (float*)d_out;

    k_init<<<1, 128>>>();
    k_transp<<<1024, 256>>>(Wh2h);
    k_run<<<NCONS + NPROD, 256>>>(input, Wi2h, hspk0, hmem0, omem0,
                                  bi2h, bh2h, thr_h, Wh2o, bh2o, thr_o);
    k_filt<<<BH / 128, 128>>>(out);
    k_final<<<1, 256>>>(labels, out);
}

// round 15
// speedup vs baseline: 1.2820x; 1.2041x over previous
#include <cuda_runtime.h>
#include <math.h>

#define Bb 128
#define Tt 100
#define Dd 2048
#define Hh 1024
#define Oo 20
#define BH (Bb*Hh)          // 131072
#define TW 91               // T - W + 1
#define NCONS 128
#define NPROD 160
#define NTILES (Tt*8)       // 800: 8 n-tiles per t-slice

typedef unsigned long long ull;

__device__ __forceinline__ void ffma2(ull& d, ull a, ull b) {
    asm("fma.rn.f32x2 %0, %1, %2, %0;" : "+l"(d) : "l"(a), "l"(b));
}
__device__ __forceinline__ ull bcast2(float x) {
    ull r; unsigned xi = __float_as_uint(x);
    asm("mov.b64 %0, {%1, %2};" : "=l"(r) : "r"(xi), "r"(xi));
    return r;
}
union f4u2 { float4 f; ull u[2]; };

// ---------------- device scratch ----------
__device__ float g_A[Tt*BH];         // input projection G1, layout [t][b][h]
__device__ float g_S[Tt*BH];         // spike history [t][b*H+h]
__device__ float g_WT[Hh*Hh];        // Wh2h transposed: WT[k][n]
__device__ float g_osum[Bb*Oo];
__device__ float g_nbr[Tt];
__device__ int   g_ready[Tt];        // producer->consumer slice flags

// ---------------- init -------------------------------------------------------
__global__ void k_init() {
    int idx = blockIdx.x * blockDim.x + threadIdx.x;
    if (idx < Tt) { g_nbr[idx] = 0.f; g_ready[idx] = 0; }
}

// ---------------- transpose Wh2h -> WT[k][n] --------------------------------
__global__ __launch_bounds__(256) void k_transp(const float* __restrict__ W) {
    __shared__ float tile[32][33];
    int bx = blockIdx.x % 32, by = blockIdx.x / 32;
    int lx = threadIdx.x & 31, ly = threadIdx.x >> 5;
#pragma unroll
    for (int r = 0; r < 4; r++) {
        int n = by * 32 + ly + r * 8;
        tile[ly + r * 8][lx] = W[(size_t)n * Hh + bx * 32 + lx];
    }
    __syncthreads();
#pragma unroll
    for (int r = 0; r < 4; r++) {
        int k = bx * 32 + ly + r * 8;
        g_WT[(size_t)k * Hh + by * 32 + lx] = tile[lx][ly + r * 8];
    }
}

// ---------------- shared-memory union ---------------------------------------
struct SmemProd {
    float As[2][16][132];
    float Bs[2][16][132];
};
struct SmemCons {
    float sflag[Hh];
    int   list[Hh];
    float red[8];
    float rs[Oo][128];
    float spsm[Oo];
    float omem[Oo];
    float osum[Oo];
    int   cnt;
};
union SmemU { SmemProd p; SmemCons c; };

// ---------------- the persistent everything kernel --------------------------
// grid 288 x 256, __launch_bounds__(256,2): all blocks resident wave 0.
//   blocks 0..127   : consumer — full 100-step recursion for batch b=bid
//   blocks 128..287 : producers — f32x2 input-GEMM tiles, static stride (5 ea)
__global__ __launch_bounds__(256, 2) void k_run(
    const float* __restrict__ X,   const float* __restrict__ W1,
    const float* __restrict__ hs0, const float* __restrict__ hm0,
    const float* __restrict__ om0,
    const float* __restrict__ b1,  const float* __restrict__ b2,
    const float* __restrict__ thr_h,
    const float* __restrict__ W2,  const float* __restrict__ b2o,
    const float* __restrict__ thr_o)
{
    __shared__ SmemU sm;
    const int tid = threadIdx.x;
    const int bid = blockIdx.x;

    if (bid >= NCONS) {
        // ================= PRODUCER (identical to R11) =================
        const int lr = tid >> 2;
        const int lc = (tid & 3) << 2;
        const int tm = tid & 15, tn = tid >> 4;

        for (int id = bid - NCONS; id < NTILES; id += NPROD) {
            const int t  = id >> 3;
            const int n0 = (id & 7) * 128;

            ull c2[8][4];
#pragma unroll
            for (int i = 0; i < 8; i++)
#pragma unroll
                for (int p = 0; p < 4; p++) c2[i][p] = 0ULL;

            const float* pa0 = X + (size_t)lr * (Tt * Dd) + (size_t)t * Dd + lc;
            const float* pa1 = X + (size_t)(lr + 64) * (Tt * Dd) + (size_t)t * Dd + lc;
            const float* pb0 = W1 + (size_t)(n0 + lr) * Dd + lc;
            const float* pb1 = W1 + (size_t)(n0 + lr + 64) * Dd + lc;

            float4 ra0 = *(const float4*)(pa0);
            float4 ra1 = *(const float4*)(pa1);
            float4 rb0 = *(const float4*)(pb0);
            float4 rb1 = *(const float4*)(pb1);
#pragma unroll
            for (int j = 0; j < 4; j++) {
                sm.p.As[0][lc + j][lr]      = ((const float*)&ra0)[j];
                sm.p.As[0][lc + j][lr + 64] = ((const float*)&ra1)[j];
                sm.p.Bs[0][lc + j][lr]      = ((const float*)&rb0)[j];
                sm.p.Bs[0][lc + j][lr + 64] = ((const float*)&rb1)[j];
            }
            __syncthreads();

            const int NK = Dd / 16;
            int buf = 0;
            for (int kt = 0; kt < NK; ++kt) {
                if (kt + 1 < NK) {
                    int ko = (kt + 1) * 16;
                    ra0 = *(const float4*)(pa0 + ko);
                    ra1 = *(const float4*)(pa1 + ko);
                    rb0 = *(const float4*)(pb0 + ko);
                    rb1 = *(const float4*)(pb1 + ko);
                }
#pragma unroll
                for (int kk = 0; kk < 16; ++kk) {
                    float4 a0 = *(const float4*)&sm.p.As[buf][kk][tm * 4];
                    float4 a1 = *(const float4*)&sm.p.As[buf][kk][tm * 4 + 64];
                    f4u2 b0u, b1u;
                    b0u.f = *(const float4*)&sm.p.Bs[buf][kk][tn * 4];
                    b1u.f = *(const float4*)&sm.p.Bs[buf][kk][tn * 4 + 64];
                    ull bp[4] = {b0u.u[0], b0u.u[1], b1u.u[0], b1u.u[1]};
                    float av[8] = {a0.x,a0.y,a0.z,a0.w,a1.x,a1.y,a1.z,a1.w};
#pragma unroll
                    for (int i = 0; i < 8; i++) {
                        ull ap = bcast2(av[i]);
#pragma unroll
                        for (int p = 0; p < 4; p++) ffma2(c2[i][p], ap, bp[p]);
                    }
                }
                if (kt + 1 < NK) {
                    int nb = buf ^ 1;
#pragma unroll
                    for (int j = 0; j < 4; j++) {
                        sm.p.As[nb][lc + j][lr]      = ((const float*)&ra0)[j];
                        sm.p.As[nb][lc + j][lr + 64] = ((const float*)&ra1)[j];
                        sm.p.Bs[nb][lc + j][lr]      = ((const float*)&rb0)[j];
                        sm.p.Bs[nb][lc + j][lr + 64] = ((const float*)&rb1)[j];
                    }
                }
                buf ^= 1;
                __syncthreads();
            }

#pragma unroll
            for (int i = 0; i < 8; i++) {
                int row = tm * 4 + (i & 3) + ((i >= 4) ? 64 : 0);
#pragma unroll
                for (int jg = 0; jg < 2; jg++) {
                    f4u2 v;
                    v.u[0] = c2[i][2 * jg];
                    v.u[1] = c2[i][2 * jg + 1];
                    *(float4*)&g_A[((size_t)t * Bb + row) * Hh + n0 + tn * 4 + jg * 64] = v.f;
                }
            }
            __threadfence();
            __syncthreads();
            if (tid == 0) atomicAdd(&g_ready[t], 1);
        }
        return;
    }

    // ================= CONSUMER: batch b = bid, all 100 steps =================
    const int b = bid;
    const int lane = tid & 31;
    const int wid = tid >> 5;

    float4 hm4 = *(const float4*)&hm0[(size_t)b * Hh + tid * 4];
    float mreg[4] = {hm4.x, hm4.y, hm4.z, hm4.w};
    float4 bb1 = *(const float4*)&b1[tid * 4];
    float4 bb2 = *(const float4*)&b2[tid * 4];
    float4 th4 = *(const float4*)&thr_h[tid * 4];
    float b1v[4] = {bb1.x, bb1.y, bb1.z, bb1.w};
    float b2v[4] = {bb2.x, bb2.y, bb2.z, bb2.w};
    float thv[4] = {th4.x, th4.y, th4.z, th4.w};

    *(float4*)&sm.c.sflag[tid * 4] = *(const float4*)&hs0[(size_t)b * Hh + tid * 4];
    if (tid < Oo) {
        sm.c.omem[tid] = om0[b * Oo + tid];
        sm.c.osum[tid] = 0.f;
    }
    __syncthreads();

    // initial ordered compaction for t=0 (warp 0)
    if (tid < 32) {
        int base = 0;
        for (int c = 0; c < 32; ++c) {
            float v = sm.c.sflag[c * 32 + tid];
            unsigned m = __ballot_sync(0xffffffffu, v != 0.f);
            if (v != 0.f) {
                int pre = __popc(m & ((1u << tid) - 1u));
                sm.c.list[base + pre] = c * 32 + tid;
            }
            base += __popc(m);
        }
        if (tid == 0) sm.c.cnt = base;
    }
    __syncthreads();

    for (int t = 0; t < Tt; ++t) {
        const int cnt = sm.c.cnt;

        // ---- sparse gather, 8-wide MLP (adds stay ascending-k: bit-exact) ----
        float a0 = 0.f, a1 = 0.f, a2 = 0.f, a3 = 0.f;
        int j = 0;
        for (; j + 8 <= cnt; j += 8) {
            float4 w0 = *(const float4*)&g_WT[(size_t)sm.c.list[j    ] * Hh + tid * 4];
            float4 w1 = *(const float4*)&g_WT[(size_t)sm.c.list[j + 1] * Hh + tid * 4];
            float4 w2 = *(const float4*)&g_WT[(size_t)sm.c.list[j + 2] * Hh + tid * 4];
            float4 w3 = *(const float4*)&g_WT[(size_t)sm.c.list[j + 3] * Hh + tid * 4];
            float4 w4 = *(const float4*)&g_WT[(size_t)sm.c.list[j + 4] * Hh + tid * 4];
            float4 w5 = *(const float4*)&g_WT[(size_t)sm.c.list[j + 5] * Hh + tid * 4];
            float4 w6 = *(const float4*)&g_WT[(size_t)sm.c.list[j + 6] * Hh + tid * 4];
            float4 w7 = *(const float4*)&g_WT[(size_t)sm.c.list[j + 7] * Hh + tid * 4];
            a0 += w0.x; a1 += w0.y; a2 += w0.z; a3 += w0.w;
            a0 += w1.x; a1 += w1.y; a2 += w1.z; a3 += w1.w;
            a0 += w2.x; a1 += w2.y; a2 += w2.z; a3 += w2.w;
            a0 += w3.x; a1 += w3.y; a2 += w3.z; a3 += w3.w;
            a0 += w4.x; a1 += w4.y; a2 += w4.z; a3 += w4.w;
            a0 += w5.x; a1 += w5.y; a2 += w5.z; a3 += w5.w;
            a0 += w6.x; a1 += w6.y; a2 += w6.z; a3 += w6.w;
            a0 += w7.x; a1 += w7.y; a2 += w7.z; a3 += w7.w;
        }
        for (; j < cnt; ++j) {
            float4 w = *(const float4*)&g_WT[(size_t)sm.c.list[j] * Hh + tid * 4];
            a0 += w.x; a1 += w.y; a2 += w.z; a3 += w.w;
        }

        // ---- wait for input slice t ----
        if (tid == 0) {
            while (*((volatile int*)&g_ready[t]) < 8) __nanosleep(64);
            __threadfence();
        }
        __syncthreads();                                   // barrier A

        // ---- hidden membrane update ----
        float accs[4] = {a0, a1, a2, a3};
        float4 G1 = *(const float4*)&g_A[((size_t)t * Bb + b) * Hh + tid * 4];
        float g1v[4] = {G1.x, G1.y, G1.z, G1.w};
        float spv[4];
        float spsum = 0.f;
#pragma unroll
        for (int e = 0; e < 4; e++) {
            float v = ((g1v[e] + b1v[e]) + accs[e]) + b2v[e];
            float mem = mreg[e] + v;
            float th = thv[e];
            float sp = (mem - th > 0.f) ? 1.f : 0.f;
            mem = mem * (1.f - sp);
            float neg = (mem < -th) ? 1.f : 0.f;
            mem = mem * (1.f - neg) - th * neg;
            mreg[e] = mem;
            spv[e] = sp;
            spsum += sp;
        }
        float4 spq = make_float4(spv[0], spv[1], spv[2], spv[3]);
        *(float4*)&g_S[(size_t)t * BH + b * Hh + tid * 4] = spq;
        *(float4*)&sm.c.sflag[tid * 4] = spq;

        // hidden-spike count: warp shuffle reduce (dyadic-exact, order-free)
#pragma unroll
        for (int off = 16; off > 0; off >>= 1)
            spsum += __shfl_down_sync(0xffffffffu, spsum, off);
        if (lane == 0) sm.c.red[wid] = spsum;
        __syncthreads();                                   // barrier B
        if (tid == 0) {
            float s = 0.f;
#pragma unroll
            for (int w = 0; w < 8; w++) s += sm.c.red[w];
            atomicAdd(&g_nbr[t], s * (1.f / Bb));
        }

        // ---- parallel: output-layer partial (warps 0-3) + compaction (warp 7)
        if (tid < 128) {
            float acc[Oo];
#pragma unroll
            for (int o = 0; o < Oo; o++) acc[o] = 0.f;
            for (int k = tid; k < Hh; k += 128) {
                float h = sm.c.sflag[k];
#pragma unroll
                for (int o = 0; o < Oo; o++) acc[o] = fmaf(h, W2[o * Hh + k], acc[o]);
            }
#pragma unroll
            for (int o = 0; o < Oo; o++) sm.c.rs[o][tid] = acc[o];
        } else if (tid >= 224) {
            // build list for step t+1 from current sflag (indices only: bit-safe)
            int base = 0;
            for (int c = 0; c < 32; ++c) {
                float v = sm.c.sflag[c * 32 + lane];
                unsigned m = __ballot_sync(0xffffffffu, v != 0.f);
                if (v != 0.f) {
                    int pre = __popc(m & ((1u << lane) - 1u));
                    sm.c.list[base + pre] = c * 32 + lane;
                }
                base += __popc(m);
            }
            if (lane == 0) sm.c.cnt = base;
        }
        __syncthreads();                                   // barrier C

        // exact tree reduction: full barriers only while cross-warp
        if (tid < 64)
#pragma unroll
            for (int o = 0; o < Oo; o++) sm.c.rs[o][tid] += sm.c.rs[o][tid + 64];
        __syncthreads();                                   // barrier D
        if (tid < 32) {
#pragma unroll
            for (int o = 0; o < Oo; o++) sm.c.rs[o][tid] += sm.c.rs[o][tid + 32];
            __syncwarp();
#pragma unroll
            for (int s = 16; s > 0; s >>= 1) {
                if (tid < s)
#pragma unroll
                    for (int o = 0; o < Oo; o++) sm.c.rs[o][tid] += sm.c.rs[o][tid + s];
                __syncwarp();
            }
            // output membrane update (threads 0..19, all in warp 0)
            if (tid < Oo) {
                int o = tid;
                float m = sm.c.omem[o] + (sm.c.rs[o][0] + b2o[o]);
                float th = thr_o[o];
                float sp = (m - th > 0.f) ? 1.f : 0.f;
                m = m * (1.f - sp);
                float neg = (m < -th) ? 1.f : 0.f;
                m = m * (1.f - neg) - th * neg;
                sm.c.omem[o] = m;
                sm.c.osum[o] += sp;
                sm.c.spsm[o] = sp;
            }
            __syncwarp();
            if (tid == 0) {
                float s = 0.f;
                for (int o = 0; o < Oo; o++) s += sm.c.spsm[o];
                atomicAdd(&g_nbr[t], s * (1.f / Bb));
            }
        }
        __syncthreads();                                   // barrier E (loop end)
    }

    if (tid < Oo) g_osum[b * Oo + tid] = sm.c.osum[tid];
}

// ---------------- sliding-window filter ------------------------------------
__global__ __launch_bounds__(128) void k_filt(float* __restrict__ out) {
    __shared__ float smf[128 * TW];
    int bh = blockIdx.x * 128 + threadIdx.x;
    const float* S = g_S + bh;
    float s = 0.f;
#pragma unroll
    for (int tt = 0; tt < 10; ++tt) s += S[(size_t)tt * BH];
    smf[threadIdx.x * TW + 0] = s / 10.0f;
    for (int tt = 10; tt < Tt; ++tt) {
        s += S[(size_t)tt * BH] - S[(size_t)(tt - 10) * BH];
        smf[threadIdx.x * TW + (tt - 9)] = s / 10.0f;
    }
    __syncthreads();
    float* dst = out + 229 + (size_t)blockIdx.x * 128 * TW;
    for (int idx = threadIdx.x; idx < 128 * TW; idx += 128) dst[idx] = smf[idx];
}

// ---------------- predictions / loss / nbr_events --------------------------
__global__ void k_final(const int* __restrict__ labels, float* __restrict__ out) {
    int tid = threadIdx.x;  // 256 threads
    __shared__ float red[128];
    if (tid < 128) {
        int b = tid;
        float mx = g_osum[b * Oo];
        int arg = 0;
        for (int o = 1; o < Oo; o++) {
            float v = g_osum[b * Oo + o];
            if (v > mx) { mx = v; arg = o; }
        }
        float se = 0.f;
        for (int o = 0; o < Oo; o++) se += expf(g_osum[b * Oo + o] - mx);
        float lse = mx + logf(se);
        out[b] = (float)arg;
        int lab = labels[b];
        red[b] = -(g_osum[b * Oo + lab] - lse);
    }
    __syncthreads();
    for (int s = 64; s > 0; s >>= 1) {
        if (tid < s) red[tid] += red[tid + s];
        __syncthreads();
    }
    if (tid == 0) out[128] = red[0] / (float)Bb;
    if (tid >= 128 && tid < 128 + Tt) out[129 + (tid - 128)] = g_nbr[tid - 128];
}

// ---------------- launcher --------------------------------------------------
extern "C" void kernel_launch(void* const* d_in, const int* in_sizes, int n_in,
                              void* d_out, int out_size) {
    const float* input = (const float*)d_in[0];
    const int*   labels = (const int*)d_in[1];
    const float* hmem0 = (const float*)d_in[2];
    const float* hspk0 = (const float*)d_in[3];
    const float* omem0 = (const float*)d_in[4];
    const float* Wi2h  = (const float*)d_in[6];
    const float* bi2h  = (const float*)d_in[7];
    const float* Wh2h  = (const float*)d_in[8];
    const float* bh2h  = (const float*)d_in[9];
    const float* Wh2o  = (const float*)d_in[10];
    const float* bh2o  = (const float*)d_in[11];
    const float* thr_h = (const float*)d_in[12];
    const float* thr_o = (const float*)d_in[13];
    float* out = (float*)d_out;

    k_init<<<1, 128>>>();
    k_transp<<<1024, 256>>>(Wh2h);
    k_run<<<NCONS + NPROD, 256>>>(input, Wi2h, hspk0, hmem0, omem0,
                                  bi2h, bh2h, thr_h, Wh2o, bh2o, thr_o);
    k_filt<<<BH / 128, 128>>>(out);
    k_final<<<1, 256>>>(labels, out);
}